// round 2
// baseline (speedup 1.0000x reference)
#include <cuda_runtime.h>

// Problem constants
#define S_GRID 14
#define NBOX   2
#define NCLS   20
#define N_IMG  4096
#define CELLS  (N_IMG * S_GRID * S_GRID)   // 802816
#define PRED_C (NBOX * 5 + NCLS)           // 30

// Global accumulators: [0]=cls, [1]=noobj, [2]=containing, [3]=reg(center+dim)
__device__ double g_acc[4];

__global__ void zero_acc_kernel() {
    if (threadIdx.x < 4) g_acc[threadIdx.x] = 0.0;
}

__global__ void __launch_bounds__(256) yolo_loss_kernel(
    const float* __restrict__ pred,   // [CELLS, 30]
    const float* __restrict__ tbox,   // [CELLS, 4]
    const float* __restrict__ tcls,   // [CELLS, 20]
    const int*   __restrict__ mask)   // [CELLS] (bool serialized as int32)
{
    const int i = blockIdx.x * blockDim.x + threadIdx.x;

    float cls_s = 0.f, noobj_s = 0.f, cont_s = 0.f, reg_s = 0.f;

    if (i < CELLS) {
        // ---- load pred row (120 B, 8-byte aligned for every i) ----
        float p[PRED_C];
        const float2* p2 = reinterpret_cast<const float2*>(pred + (size_t)i * PRED_C);
        #pragma unroll
        for (int j = 0; j < PRED_C / 2; j++) {
            float2 v = p2[j];
            p[2 * j]     = v.x;
            p[2 * j + 1] = v.y;
        }

        // ---- target box (16-byte aligned) ----
        const float4 tb = reinterpret_cast<const float4*>(tbox)[i];

        const float m = (mask[i] != 0) ? 1.0f : 0.0f;

        // ---- class loss: m * sum (pred_cls - target_cls)^2 ----
        const float4* tc4 = reinterpret_cast<const float4*>(tcls + (size_t)i * NCLS);
        float s = 0.f;
        #pragma unroll
        for (int j = 0; j < NCLS / 4; j++) {
            float4 c = tc4[j];
            float d0 = p[10 + 4 * j + 0] - c.x;
            float d1 = p[10 + 4 * j + 1] - c.y;
            float d2 = p[10 + 4 * j + 2] - c.z;
            float d3 = p[10 + 4 * j + 3] - c.w;
            s += d0 * d0 + d1 * d1 + d2 * d2 + d3 * d3;
        }
        cls_s = m * s;

        // ---- no-object loss: (1-m) * sum_b conf_b^2 ----
        const float c0 = p[4], c1 = p[9];
        noobj_s = (1.0f - m) * (c0 * c0 + c1 * c1);

        // ---- IoU per box ----
        float iou[NBOX];
        #pragma unroll
        for (int b = 0; b < NBOX; b++) {
            const float x = p[5 * b + 0] * (1.0f / S_GRID);
            const float y = p[5 * b + 1] * (1.0f / S_GRID);
            const float w = p[5 * b + 2];
            const float h = p[5 * b + 3];
            const float p1x = x - w * 0.5f, p1y = y - h * 0.5f;
            const float p2x = x + w * 0.5f, p2y = y + h * 0.5f;
            const float ltx = fmaxf(p1x, tb.x), lty = fmaxf(p1y, tb.y);
            const float rbx = fminf(p2x, tb.z), rby = fminf(p2y, tb.w);
            const float iw = fmaxf(rbx - ltx, 0.0f);
            const float ih = fmaxf(rby - lty, 0.0f);
            const float inter = iw * ih;
            const float area_p = w * h;
            const float area_t = (tb.z - tb.x) * (tb.w - tb.y);
            iou[b] = inter / (area_p + area_t - inter);
        }

        // argmax over B=2 (first occurrence of max, like jnp.argmax)
        const bool pick1 = (iou[1] > iou[0]);

        // select best box WITHOUT dynamic indexing (keeps p[] in registers)
        const float bx = pick1 ? p[5] : p[0];
        const float by = pick1 ? p[6] : p[1];
        const float bw = pick1 ? p[7] : p[2];
        const float bh = pick1 ? p[8] : p[3];
        const float bc = pick1 ? p[9] : p[4];

        // ---- containing-object loss ----
        cont_s = m * (bc - 1.0f) * (bc - 1.0f);

        // ---- regression loss (center + dim) ----
        const float dx = bx - tb.x;
        const float dy = by - tb.y;
        const float dw = sqrtf(bw) - sqrtf(tb.z);
        const float dh = sqrtf(bh) - sqrtf(tb.w);
        reg_s = m * (dx * dx + dy * dy + dw * dw + dh * dh);
    }

    // ---- block reduction: warp shuffle, then shared across warps ----
    #pragma unroll
    for (int off = 16; off > 0; off >>= 1) {
        cls_s   += __shfl_down_sync(0xFFFFFFFFu, cls_s,   off);
        noobj_s += __shfl_down_sync(0xFFFFFFFFu, noobj_s, off);
        cont_s  += __shfl_down_sync(0xFFFFFFFFu, cont_s,  off);
        reg_s   += __shfl_down_sync(0xFFFFFFFFu, reg_s,   off);
    }

    __shared__ float sh[4][8];  // 256 threads -> 8 warps
    const int wid = threadIdx.x >> 5;
    const int lid = threadIdx.x & 31;
    if (lid == 0) {
        sh[0][wid] = cls_s;
        sh[1][wid] = noobj_s;
        sh[2][wid] = cont_s;
        sh[3][wid] = reg_s;
    }
    __syncthreads();

    if (wid == 0) {
        float v0 = (lid < 8) ? sh[0][lid] : 0.f;
        float v1 = (lid < 8) ? sh[1][lid] : 0.f;
        float v2 = (lid < 8) ? sh[2][lid] : 0.f;
        float v3 = (lid < 8) ? sh[3][lid] : 0.f;
        #pragma unroll
        for (int off = 4; off > 0; off >>= 1) {
            v0 += __shfl_down_sync(0xFFFFFFFFu, v0, off);
            v1 += __shfl_down_sync(0xFFFFFFFFu, v1, off);
            v2 += __shfl_down_sync(0xFFFFFFFFu, v2, off);
            v3 += __shfl_down_sync(0xFFFFFFFFu, v3, off);
        }
        if (lid == 0) {
            atomicAdd(&g_acc[0], (double)v0);
            atomicAdd(&g_acc[1], (double)v1);
            atomicAdd(&g_acc[2], (double)v2);
            atomicAdd(&g_acc[3], (double)v3);
        }
    }
}

__global__ void finalize_kernel(float* __restrict__ out) {
    const double inv_n = 1.0 / (double)N_IMG;
    const double cls   = g_acc[0] * inv_n;
    const double noobj = g_acc[1] * inv_n;
    const double cont  = g_acc[2] * inv_n;
    const double reg   = g_acc[3] * inv_n;
    const double total = cls + 0.5 * noobj + 5.0 * reg + cont;
    out[0] = (float)total;
    out[1] = (float)reg;
    out[2] = (float)cont;
    out[3] = (float)noobj;
    out[4] = (float)cls;
}

extern "C" void kernel_launch(void* const* d_in, const int* in_sizes, int n_in,
                              void* d_out, int out_size) {
    // Identify inputs by element count (robust to ordering):
    //   pred: 24,084,480   tbox: 3,211,264   tcls: 16,056,320   mask: 802,816
    const float* pred = nullptr;
    const float* tbox = nullptr;
    const float* tcls = nullptr;
    const int*   msk  = nullptr;
    for (int k = 0; k < n_in; k++) {
        const long long sz = in_sizes[k];
        if      (sz == (long long)CELLS * PRED_C) pred = (const float*)d_in[k];
        else if (sz == (long long)CELLS * 4)      tbox = (const float*)d_in[k];
        else if (sz == (long long)CELLS * NCLS)   tcls = (const float*)d_in[k];
        else if (sz == (long long)CELLS)          msk  = (const int*)d_in[k];
    }
    float* out = (float*)d_out;

    zero_acc_kernel<<<1, 32>>>();
    const int threads = 256;
    const int blocks = (CELLS + threads - 1) / threads;  // 3136
    yolo_loss_kernel<<<blocks, threads>>>(pred, tbox, tcls, msk);
    finalize_kernel<<<1, 1>>>(out);
}